// round 5
// baseline (speedup 1.0000x reference)
#include <cuda_runtime.h>
#include <math.h>

#define NN 100000
#define NE 1600000
#define C  128
#define OC 64
#define NG 64

// ---------------- static device scratch (zero-initialized .bss) --------------
__device__ float g_bufA[(size_t)NN * C];
__device__ float g_bufB[(size_t)NN * C];
__device__ int   g_col[NE];
__device__ int   g_cnt[NN];        // in-degree (no self loop); re-zeroed by k_cleanup
__device__ int   g_rowptr[NN];
__device__ int   g_fillptr[NN];
__device__ float g_dinv[NN];
__device__ int   g_gcnt[NG];       // re-zeroed by k_cleanup
__device__ int   g_goff[NG + 1];
__device__ float g_pool[NG * C];

__device__ __forceinline__ int detect64(const int* e32) {
    int is64 = 1;
    #pragma unroll
    for (int i = 0; i < 8; i++) if (e32[2 * i + 1] != 0) is64 = 0;
    return is64;
}

// idx 0: in-degree histogram + per-graph node histogram (counters pre-zeroed)
__global__ void k_hist_all(const void* ei, const void* bat, int E, int N) {
    int tid = blockIdx.x * blockDim.x + threadIdx.x;
    int stride = gridDim.x * blockDim.x;
    int is64 = detect64((const int*)ei);
    if (is64) {
        const long long* e = (const long long*)ei;
        for (int i = tid; i < E; i += stride)
            atomicAdd(&g_cnt[(int)e[(size_t)E + i]], 1);
        const long long* b = (const long long*)bat;
        for (int i = tid; i < N; i += stride) atomicAdd(&g_gcnt[(int)b[i]], 1);
    } else {
        const int* e = (const int*)ei;
        for (int i = tid; i < E; i += stride)
            atomicAdd(&g_cnt[e[E + i]], 1);
        const int* b = (const int*)bat;
        for (int i = tid; i < N; i += stride) atomicAdd(&g_gcnt[b[i]], 1);
    }
}

// idx 1: single-block chunked exclusive scan (shuffle) + dinv + fillptr init
__global__ void k_scan(int n) {
    __shared__ int wsum[32];
    __shared__ int carry_s;
    int tid = threadIdx.x;
    int lane = tid & 31, wid = tid >> 5;
    if (tid == 0) carry_s = 0;
    __syncthreads();

    for (int base = 0; base < n; base += 1024) {
        int i = base + tid;
        int v = (i < n) ? g_cnt[i] : 0;
        int x = v;
        #pragma unroll
        for (int o = 1; o < 32; o <<= 1) {
            int t = __shfl_up_sync(~0u, x, o);
            if (lane >= o) x += t;
        }
        if (lane == 31) wsum[wid] = x;
        __syncthreads();
        if (wid == 0) {
            int s = wsum[lane];
            #pragma unroll
            for (int o = 1; o < 32; o <<= 1) {
                int t = __shfl_up_sync(~0u, s, o);
                if (lane >= o) s += t;
            }
            wsum[lane] = s;
        }
        __syncthreads();
        int carry = carry_s;
        int warpoff = (wid > 0) ? wsum[wid - 1] : 0;
        int excl = carry + warpoff + x - v;
        if (i < n) {
            g_rowptr[i] = excl;
            g_fillptr[i] = excl;
            g_dinv[i] = rsqrtf((float)(v + 1));
        }
        __syncthreads();
        if (tid == 1023) carry_s = carry + wsum[31];
        __syncthreads();
    }
}

// idx 2: CSR column fill via atomic cursors (measured 27us)
__global__ void k_fill(const void* ei, int E) {
    int tid = blockIdx.x * blockDim.x + threadIdx.x;
    int stride = gridDim.x * blockDim.x;
    int is64 = detect64((const int*)ei);
    if (is64) {
        const long long* e = (const long long*)ei;
        for (int i = tid; i < E; i += stride) {
            int d = (int)e[(size_t)E + i];
            int s = (int)e[i];
            g_col[atomicAdd(&g_fillptr[d], 1)] = s;
        }
    } else {
        const int* e = (const int*)ei;
        for (int i = tid; i < E; i += stride) {
            int d = e[E + i];
            int s = e[i];
            g_col[atomicAdd(&g_fillptr[d], 1)] = s;
        }
    }
}

// idx 3 (PROFILED) etc: z_i = dinv_i*(dinv_i*x_i + sum_j dinv_j*x_j)
// Channel-split: one launch covers 64 channels (pass 0: ch 0-63, pass 1: ch 64-127)
// so the gather working set (25.6 MB) is L2-resident.
// Each warp = 2 nodes; half-warp (16 lanes) x float4 = 64 channels per node.
__global__ __launch_bounds__(256) void k_agg64(
    const float* __restrict__ Xin, float* __restrict__ Zout, int n, int pass)
{
    int gwarp = (blockIdx.x * blockDim.x + threadIdx.x) >> 5;
    int lane = threadIdx.x & 31;
    int half = lane >> 4;
    int hl   = lane & 15;
    int node = gwarp * 2 + half;
    if (node >= n) return;

    const float4* X4 = (const float4*)Xin;
    int poff = pass * 16;
    size_t rowbase = (size_t)node * 32 + poff + hl;

    float di = g_dinv[node];
    float4 s4 = X4[rowbase];
    float4 acc = make_float4(s4.x * di, s4.y * di, s4.z * di, s4.w * di);

    int e = g_rowptr[node];
    int end = e + g_cnt[node];

    for (; e + 8 <= end; e += 8) {
        int s[8];
        #pragma unroll
        for (int j = 0; j < 8; j++) s[j] = g_col[e + j];
        float w[8];
        #pragma unroll
        for (int j = 0; j < 8; j++) w[j] = g_dinv[s[j]];
        float4 v[8];
        #pragma unroll
        for (int j = 0; j < 8; j++) v[j] = X4[(size_t)s[j] * 32 + poff + hl];
        #pragma unroll
        for (int j = 0; j < 8; j++) {
            acc.x = fmaf(w[j], v[j].x, acc.x);
            acc.y = fmaf(w[j], v[j].y, acc.y);
            acc.z = fmaf(w[j], v[j].z, acc.z);
            acc.w = fmaf(w[j], v[j].w, acc.w);
        }
    }
    for (; e < end; e++) {
        int s = g_col[e];
        float w = g_dinv[s];
        float4 v = X4[(size_t)s * 32 + poff + hl];
        acc.x = fmaf(w, v.x, acc.x);
        acc.y = fmaf(w, v.y, acc.y);
        acc.z = fmaf(w, v.z, acc.z);
        acc.w = fmaf(w, v.w, acc.w);
    }

    ((float4*)Zout)[rowbase] =
        make_float4(di * acc.x, di * acc.y, di * acc.z, di * acc.w);
}

// gemm: H = relu(Z @ W + b)  64-row tile, full W in smem (measured 317us)
__global__ __launch_bounds__(256, 2) void k_gemm(
    const float* __restrict__ Z, const float* __restrict__ W,
    const float* __restrict__ bias, float* __restrict__ H, int n)
{
    __shared__ float Ws[C * C];
    __shared__ float Zs[64 * C];
    int tid = threadIdx.x;
    int row0 = blockIdx.x * 64;

    for (int i = tid; i < C * C; i += 256) Ws[i] = W[i];
    for (int i = tid; i < 64 * C; i += 256) {
        int r = row0 + (i >> 7);
        Zs[i] = (r < n) ? Z[(size_t)r * C + (i & 127)] : 0.0f;
    }
    __syncthreads();

    int tn = tid & 31;
    int tm = tid >> 5;
    float acc[8][4];
    #pragma unroll
    for (int r = 0; r < 8; r++)
        #pragma unroll
        for (int c = 0; c < 4; c++) acc[r][c] = 0.0f;

    #pragma unroll 4
    for (int k = 0; k < C; k++) {
        float4 wv = *(const float4*)&Ws[k * C + tn * 4];
        #pragma unroll
        for (int r = 0; r < 8; r++) {
            float zv = Zs[(tm * 8 + r) * C + k];
            acc[r][0] += zv * wv.x;
            acc[r][1] += zv * wv.y;
            acc[r][2] += zv * wv.z;
            acc[r][3] += zv * wv.w;
        }
    }

    float4 bv = ((const float4*)bias)[tn];
    #pragma unroll
    for (int r = 0; r < 8; r++) {
        int row = row0 + tm * 8 + r;
        if (row < n) {
            float4 o;
            o.x = fmaxf(acc[r][0] + bv.x, 0.f);
            o.y = fmaxf(acc[r][1] + bv.y, 0.f);
            o.z = fmaxf(acc[r][2] + bv.z, 0.f);
            o.w = fmaxf(acc[r][3] + bv.w, 0.f);
            *(float4*)&H[(size_t)row * C + tn * 4] = o;
        }
    }
}

__global__ void k_goff() {
    __shared__ int sh[NG];
    if (threadIdx.x < NG) sh[threadIdx.x] = g_gcnt[threadIdx.x];
    __syncthreads();
    if (threadIdx.x == 0) {
        int s = 0;
        for (int g = 0; g < NG; g++) { g_goff[g] = s; s += sh[g]; }
        g_goff[NG] = s;
    }
}

__global__ void k_pool(const float* __restrict__ H) {
    __shared__ float4 sh[8][32];
    int g = blockIdx.x;
    int rr = threadIdx.x >> 5;
    int c4 = threadIdx.x & 31;
    int s = g_goff[g], e = g_goff[g + 1];
    const float4* H4 = (const float4*)H;
    float4 acc = make_float4(0.f, 0.f, 0.f, 0.f);
    for (int r = s + rr; r < e; r += 8) {
        float4 v = H4[(size_t)r * 32 + c4];
        acc.x += v.x; acc.y += v.y; acc.z += v.z; acc.w += v.w;
    }
    sh[rr][c4] = acc;
    __syncthreads();
    if (rr == 0) {
        #pragma unroll
        for (int j = 1; j < 8; j++) {
            float4 v = sh[j][c4];
            acc.x += v.x; acc.y += v.y; acc.z += v.z; acc.w += v.w;
        }
        float inv = 1.0f / fmaxf((float)(e - s), 1.0f);
        ((float4*)g_pool)[g * 32 + c4] =
            make_float4(acc.x * inv, acc.y * inv, acc.z * inv, acc.w * inv);
    }
}

__global__ void k_head(const float* __restrict__ Wl,
                       const float* __restrict__ bl,
                       float* __restrict__ out)
{
    int g = blockIdx.x;
    int o = threadIdx.x;
    float acc = bl[o];
    #pragma unroll 4
    for (int k = 0; k < C; k++) acc += g_pool[g * C + k] * Wl[k * OC + o];
    out[g * OC + o] = acc;
}

// restore zeroed counters for next replay (determinism)
__global__ void k_cleanup(int N) {
    int tid = blockIdx.x * blockDim.x + threadIdx.x;
    int stride = gridDim.x * blockDim.x;
    for (int i = tid; i < N; i += stride) g_cnt[i] = 0;
    if (tid < NG) g_gcnt[tid] = 0;
}

// ---------------- launch -----------------------------------------------------
extern "C" void kernel_launch(void* const* d_in, const int* in_sizes, int n_in,
                              void* d_out, int out_size) {
    const float* x   = (const float*)d_in[0];
    const void*  ei  = d_in[1];
    const void*  bat = d_in[2];
    const float* W1  = (const float*)d_in[3];
    const float* b1  = (const float*)d_in[4];
    const float* W2  = (const float*)d_in[5];
    const float* b2  = (const float*)d_in[6];
    const float* Wl  = (const float*)d_in[7];
    const float* bl  = (const float*)d_in[8];
    float* out = (float*)d_out;

    int N = in_sizes[0] / C;
    int E = in_sizes[1] / 2;
    int gb = (N + 63) / 64;
    int ab = (N * 16 + 255) / 256;   // agg blocks (2 nodes per warp)

    k_hist_all<<<1024, 256>>>(ei, bat, E, N);                 // 0
    k_scan    <<<1, 1024>>>(N);                               // 1
    k_fill    <<<1024, 256>>>(ei, E);                         // 2
    k_agg64   <<<ab, 256>>>(x, g_bufA, N, 0);                 // 3  <-- profiled
    k_agg64   <<<ab, 256>>>(x, g_bufA, N, 1);                 // 4
    k_gemm    <<<gb, 256>>>(g_bufA, W1, b1, g_bufB, N);       // 5
    k_agg64   <<<ab, 256>>>(g_bufB, g_bufA, N, 0);            // 6
    k_agg64   <<<ab, 256>>>(g_bufB, g_bufA, N, 1);            // 7
    k_gemm    <<<gb, 256>>>(g_bufA, W2, b2, g_bufB, N);       // 8
    k_goff    <<<1, 64>>>();                                  // 9
    k_pool    <<<NG, 256>>>(g_bufB);                          // 10
    k_head    <<<NG, OC>>>(Wl, bl, out);                      // 11
    k_cleanup <<<256, 256>>>(N);                              // 12
}